// round 16
// baseline (speedup 1.0000x reference)
#include <cuda_runtime.h>
#include <cuda_bf16.h>
#include <math.h>

// ---------------- problem constants ----------------
#define NPTS   200000
#define DF     128
#define NXC    250
#define NYC    250
#define NZC    20
#define VXYZ   1250000           // NXC*NYC*NZC
#define NVKEY  10000000          // B * VXYZ
#define NAKEY  5000000           // (B/2) * VXYZ
#define VWORDS 312500            // NVKEY/32
#define AWORDS 156250            // NAKEY/32
#define VBLOCKS 1221             // ceil(VWORDS/256)
#define ABLOCKS 611              // ceil(AWORDS/256)
#define MARK_BLOCKS 782          // ceil(NPTS/256)
#define WSPLIT_BLOCKS 96         // (3*DF/2*DF)/256
#define ZERO_BLOCKS 1024
#define GEMM_BLOCKS 3125         // NPTS/64  (64-row tiles)

// ---------------- device scratch (no allocs allowed) ----------------
__device__ unsigned g_bitV[VWORDS];
__device__ unsigned g_bitA[AWORDS];
__device__ int g_prefV[VWORDS];
__device__ int g_prefA[AWORDS];
__device__ int g_blkV[VBLOCKS];
__device__ int g_blkA[ABLOCKS];
__device__ int g_vkey[NPTS];
__device__ int g_akey[NPTS];
__device__ int g_inv[NPTS];
__device__ int g_arank[NPTS];
__device__ int g_aCl0[NPTS];   // min cluster id per associate voxel
__device__ int g_aCl1[NPTS];   // max cluster id per associate voxel (<= 2 clusters/assoc)
__device__ float g_cnt[NPTS];
__device__ float g_rowsum[NPTS];            // per-cluster sum of cfa row (separate kernel, R14-proven)
__device__ int g_mlist[NPTS];               // compacted masked point indices
__device__ int g_nMasked;
__device__ float4 g_csum4[NPTS * DF / 4];   // cluster feature sums
__device__ float4 g_cfa4[NPTS * DF / 4];    // projected cluster features
__device__ int g_K;            // max foreground inv (K = g_K+1)
__device__ int g_maskFmt;      // 0=int32, 1=byte, 2=float32
__device__ float g_scale_cp[DF], g_bias_cp[DF], g_scale_pf[DF], g_bias_pf[DF];
// pre-split weights, bf16 hi/lo planes packed as bf162 pairs along K
__device__ unsigned g_wpfH2[(3 * DF / 2) * DF], g_wpfL2[(3 * DF / 2) * DF];
__device__ unsigned g_wcpH2[(DF / 2) * DF],     g_wcpL2[(DF / 2) * DF];

// ---------------- helpers ----------------
__device__ __forceinline__ unsigned bfpack(float a, float b) {
    __nv_bfloat162 p = __halves2bfloat162(__float2bfloat16(a), __float2bfloat16(b));
    return *reinterpret_cast<unsigned*>(&p);
}

#define MMA_BF16(d, a, b) \
    asm volatile("mma.sync.aligned.m16n8k16.row.col.f32.bf16.bf16.f32 " \
                 "{%0,%1,%2,%3}, {%4,%5,%6,%7}, {%8,%9}, {%0,%1,%2,%3};\n" \
                 : "+f"((d)[0]), "+f"((d)[1]), "+f"((d)[2]), "+f"((d)[3]) \
                 : "r"((a)[0]), "r"((a)[1]), "r"((a)[2]), "r"((a)[3]), \
                   "r"((b)[0]), "r"((b)[1]))

#define CP_ASYNC16(smem_u32, gptr) \
    asm volatile("cp.async.ca.shared.global [%0], [%1], 16;" \
                 :: "r"(smem_u32), "l"(gptr) : "memory")
#define CP_ASYNC_WAIT_ALL() \
    asm volatile("cp.async.commit_group;\ncp.async.wait_group 0;" ::: "memory")

__device__ __forceinline__ bool get_fg(const void* m, int i) {
    int f = g_maskFmt;
    if (f == 0) return ((const int*)m)[i] != 0;
    if (f == 2) return ((const float*)m)[i] != 0.0f;
    return ((const unsigned char*)m)[i] != 0;
}

// ---------------- bitmap zeroing (MUST precede k_phaseA's atomicOr marks) ----------------
__global__ void k_zerobits() {
    int t = blockIdx.x * 256 + threadIdx.x;
    int stride = gridDim.x * 256;
    for (int k = t; k < VWORDS; k += stride) g_bitV[k] = 0u;
    for (int k = t; k < AWORDS; k += stride) g_bitA[k] = 0u;
}

// ---------------- phase A: mark | wsplit | detect | prep | acc-zero (fused) ----------------
__global__ void k_phaseA(const float* __restrict__ pc, const int* __restrict__ bidx,
                         const int* __restrict__ maskI,
                         const float* __restrict__ w_pf, const float* __restrict__ w_cp,
                         const float* __restrict__ b_pf, const float* __restrict__ gm_pf,
                         const float* __restrict__ be_pf, const float* __restrict__ m_pf,
                         const float* __restrict__ v_pf,
                         const float* __restrict__ b_cp, const float* __restrict__ gm_cp,
                         const float* __restrict__ be_cp, const float* __restrict__ m_cp,
                         const float* __restrict__ v_cp) {
    int b = blockIdx.x;
    int t = threadIdx.x;
    if (b < MARK_BLOCKS) {
        // ---- voxelize + mark bitmaps ----
        int i = b * 256 + t;
        if (i >= NPTS) return;
        float x = pc[3 * i + 0], y = pc[3 * i + 1], z = pc[3 * i + 2];
        int xi = (int)floorf(__fdiv_rn(x - (-50.0f), 0.4f));
        int yi = (int)floorf(__fdiv_rn(y - (-50.0f), 0.4f));
        int zi = (int)floorf(__fdiv_rn(z - (-5.0f), 0.4f));
        xi = min(max(xi, 0), NXC - 1);
        yi = min(max(yi, 0), NYC - 1);
        zi = min(max(zi, 0), NZC - 1);
        int bb = bidx[i];
        int local = (xi * NYC + yi) * NZC + zi;
        int vk = bb * VXYZ + local;
        int ak = (bb >> 1) * VXYZ + local;
        g_vkey[i] = vk;
        g_akey[i] = ak;
        atomicOr(&g_bitV[vk >> 5], 1u << (vk & 31));
        atomicOr(&g_bitA[ak >> 5], 1u << (ak & 31));
    } else if (b < MARK_BLOCKS + WSPLIT_BLOCKS) {
        // ---- weight split into bf16 hi/lo packed planes ----
        int idx = (b - MARK_BLOCKS) * 256 + t;
        if (idx < (3 * DF / 2) * DF) {
            int k2 = idx / DF, col = idx % DF;
            float x0 = w_pf[(2 * k2) * DF + col];
            float x1 = w_pf[(2 * k2 + 1) * DF + col];
            __nv_bfloat16 h0 = __float2bfloat16(x0);
            __nv_bfloat16 h1 = __float2bfloat16(x1);
            __nv_bfloat162 hp = __halves2bfloat162(h0, h1);
            g_wpfH2[idx] = *reinterpret_cast<unsigned*>(&hp);
            g_wpfL2[idx] = bfpack(x0 - __bfloat162float(h0), x1 - __bfloat162float(h1));
        }
        if (idx < (DF / 2) * DF) {
            int k2 = idx / DF, col = idx % DF;
            float x0 = w_cp[(2 * k2) * DF + col];
            float x1 = w_cp[(2 * k2 + 1) * DF + col];
            __nv_bfloat16 h0 = __float2bfloat16(x0);
            __nv_bfloat16 h1 = __float2bfloat16(x1);
            __nv_bfloat162 hp = __halves2bfloat162(h0, h1);
            g_wcpH2[idx] = *reinterpret_cast<unsigned*>(&hp);
            g_wcpL2[idx] = bfpack(x0 - __bfloat162float(h0), x1 - __bfloat162float(h1));
        }
    } else if (b == MARK_BLOCKS + WSPLIT_BLOCKS) {
        // ---- mask dtype detection ----
        int notInt = 0, notFloat = 0;
        for (int k = t; k < 1000; k += 256) {
            unsigned u = (unsigned)maskI[k];
            if (u > 1u) notInt = 1;
            if (u != 0u && u != 0x3F800000u) notFloat = 1;
        }
        notInt = __syncthreads_or(notInt);
        notFloat = __syncthreads_or(notFloat);
        if (t == 0) {
            int fmt;
            if (!notInt) fmt = 0;
            else if (!notFloat) fmt = 2;
            else fmt = 1;
            g_maskFmt = fmt;
        }
    } else if (b == MARK_BLOCKS + WSPLIT_BLOCKS + 1) {
        // ---- fold BN constants ----
        if (t < DF) {
            float s = gm_cp[t] * rsqrtf(v_cp[t] + 1e-5f);
            g_scale_cp[t] = s;
            g_bias_cp[t] = (b_cp[t] - m_cp[t]) * s + be_cp[t];
            float s2 = gm_pf[t] * rsqrtf(v_pf[t] + 1e-5f);
            g_scale_pf[t] = s2;
            g_bias_pf[t] = (b_pf[t] - m_pf[t]) * s2 + be_pf[t];
        }
        if (t == 0) { g_K = -1; g_nMasked = 0; }
    } else {
        // ---- zero-init of accumulators (consumed only by LATER launches; no race) ----
        int zb = b - (MARK_BLOCKS + WSPLIT_BLOCKS + 2);
        int idx = zb * 256 + t;
        int stride = ZERO_BLOCKS * 256;
        float4 z = make_float4(0.f, 0.f, 0.f, 0.f);
        for (int k = idx; k < NPTS * DF / 4; k += stride) g_csum4[k] = z;
        for (int k = idx; k < NPTS; k += stride) {
            g_cnt[k] = 0.f;
            g_aCl0[k] = 0x7FFFFFFF;
            g_aCl1[k] = -1;
        }
    }
}

// ---------------- bitmap popcount scan phase 1 (V and A fused) ----------------
__global__ void k_scan1() {
    int which = (blockIdx.x >= VBLOCKS) ? 1 : 0;
    int bb = which ? (blockIdx.x - VBLOCKS) : blockIdx.x;
    const unsigned* bits = which ? g_bitA : g_bitV;
    int* pref = which ? g_prefA : g_prefV;
    int* blks = which ? g_blkA : g_blkV;
    int nwords = which ? AWORDS : VWORDS;
    int w = bb * 256 + threadIdx.x;
    int c = (w < nwords) ? __popc(bits[w]) : 0;
    int lane = threadIdx.x & 31, wid = threadIdx.x >> 5;
    int v = c;
#pragma unroll
    for (int o = 1; o < 32; o <<= 1) { int u = __shfl_up_sync(0xffffffffu, v, o); if (lane >= o) v += u; }
    __shared__ int ws[8];
    if (lane == 31) ws[wid] = v;
    __syncthreads();
    if (wid == 0) {
        int x = (lane < 8) ? ws[lane] : 0;
#pragma unroll
        for (int o = 1; o < 8; o <<= 1) { int u = __shfl_up_sync(0xffffffffu, x, o); if (lane >= o) x += u; }
        if (lane < 8) ws[lane] = x;
    }
    __syncthreads();
    int incl = v + (wid > 0 ? ws[wid - 1] : 0);
    if (w < nwords) pref[w] = incl - c;
    if (threadIdx.x == 255) blks[bb] = incl;
}

// ---------------- scan phase 2 (V and A fused; 2 blocks) ----------------
__global__ void k_scan2() {
    int which = blockIdx.x;
    int nb = which ? ABLOCKS : VBLOCKS;
    int* blk = which ? g_blkA : g_blkV;
    int t = threadIdx.x;
    int i0 = 2 * t, i1 = 2 * t + 1;
    int v0 = (i0 < nb) ? blk[i0] : 0;
    int v1 = (i1 < nb) ? blk[i1] : 0;
    int s = v0 + v1;
    int lane = t & 31, wid = t >> 5;
    int v = s;
#pragma unroll
    for (int o = 1; o < 32; o <<= 1) { int u = __shfl_up_sync(0xffffffffu, v, o); if (lane >= o) v += u; }
    __shared__ int ws[32];
    if (lane == 31) ws[wid] = v;
    __syncthreads();
    if (wid == 0) {
        int x = ws[lane];
#pragma unroll
        for (int o = 1; o < 32; o <<= 1) { int u = __shfl_up_sync(0xffffffffu, x, o); if (lane >= o) x += u; }
        ws[lane] = x;
    }
    __syncthreads();
    int incl = v + (wid > 0 ? ws[wid - 1] : 0);
    int ex = incl - s;
    if (i0 < nb) blk[i0] = ex;
    if (i1 < nb) blk[i1] = ex + v0;
}

// ---------------- ranks + assoc-pair + foreground scatter-sum + out=feat (fused) ----------------
// One warp per point: lane 0 computes ranks/atomics, all lanes stream features.
__global__ void k_featacc(const float* __restrict__ feat, const void* __restrict__ maskp,
                          float* __restrict__ out) {
    int t = blockIdx.x * 256 + threadIdx.x;
    int i = t >> 5;
    if (i >= NPTS) return;
    int lane = t & 31;
    int c = 0;
    unsigned fg = 0;
    if (lane == 0) {
        int vk = g_vkey[i], ak = g_akey[i];
        int wv = vk >> 5, wa = ak >> 5;
        c = g_prefV[wv] + g_blkV[wv >> 8] + __popc(g_bitV[wv] & ((1u << (vk & 31)) - 1u));
        int a = g_prefA[wa] + g_blkA[wa >> 8] + __popc(g_bitA[wa] & ((1u << (ak & 31)) - 1u));
        g_inv[i] = c;
        g_arank[i] = a;
        atomicMin(&g_aCl0[a], c);
        atomicMax(&g_aCl1[a], c);
        fg = get_fg(maskp, i) ? 1u : 0u;
        if (fg) atomicMax(&g_K, c);
    }
    c = __shfl_sync(0xffffffffu, c, 0);
    fg = __shfl_sync(0xffffffffu, fg, 0);
    int j = lane * 4;
    float4 f = *(const float4*)&feat[(size_t)i * DF + j];
    __stcs((float4*)&out[(size_t)i * DF + j], f);   // default: out = feat (pgemm overwrites masked rows)
    if (!fg) return;
    float* cs = (float*)g_csum4 + (size_t)c * DF + j;
    atomicAdd(cs + 0, f.x);
    atomicAdd(cs + 1, f.y);
    atomicAdd(cs + 2, f.z);
    atomicAdd(cs + 3, f.w);
    if (lane == 0) atomicAdd(&g_cnt[c], 1.0f);
}

// ---------------- cluster GEMM (split-bf16, 64-row tiles) — R14-proven epilogue + hints ----------------
__global__ __launch_bounds__(256) void k_cgemm() {
    int Kv = g_K + 1;
    int row0 = blockIdx.x * 64;
    if (row0 >= Kv) return;
    __shared__ __align__(16) unsigned AsH2[8][72], AsL2[8][72];     // [k2][row] bf162
    __shared__ __align__(16) unsigned WsH2[8][136], WsL2[8][136];   // [k2][col] bf162
    __shared__ float rcs[64];
    int t = threadIdx.x;
    if (t < 64) {
        int c = row0 + t;
        rcs[t] = 1.0f / fmaxf(g_cnt[c], 1.0f);
    }
    __syncthreads();
    int r = t & 63, kl = (t >> 6) * 4;
    int lane = t & 31;
    int warpM = t >> 7;          // 0..1
    int warpN = (t >> 5) & 3;    // 0..3
    int qr = lane >> 2, qs = lane & 3;
    int wk2 = t >> 5, wc4 = (t & 31) * 4;
    unsigned sWH = (unsigned)__cvta_generic_to_shared(&WsH2[wk2][wc4]);
    unsigned sWL = (unsigned)__cvta_generic_to_shared(&WsL2[wk2][wc4]);
    float acc[2][4][4];
#pragma unroll
    for (int a = 0; a < 2; a++)
#pragma unroll
        for (int b = 0; b < 4; b++)
#pragma unroll
            for (int c = 0; c < 4; c++) acc[a][b][c] = 0.f;
    const float* csp = (const float*)g_csum4;
    for (int kt = 0; kt < 128; kt += 16) {
        CP_ASYNC16(sWH, &g_wcpH2[(kt / 2 + wk2) * DF + wc4]);
        CP_ASYNC16(sWL, &g_wcpL2[(kt / 2 + wk2) * DF + wc4]);
        float4 av = __ldcs((const float4*)&csp[(size_t)(row0 + r) * DF + kt + kl]);
        float rc = rcs[r];
        float vv[4] = {av.x * rc, av.y * rc, av.z * rc, av.w * rc};
        float lo[4];
        __nv_bfloat16 hi[4];
#pragma unroll
        for (int j = 0; j < 4; j++) {
            hi[j] = __float2bfloat16(vv[j]);
            lo[j] = vv[j] - __bfloat162float(hi[j]);
        }
        {
            __nv_bfloat162 hp0 = __halves2bfloat162(hi[0], hi[1]);
            __nv_bfloat162 hp1 = __halves2bfloat162(hi[2], hi[3]);
            AsH2[kl / 2][r]     = *reinterpret_cast<unsigned*>(&hp0);
            AsH2[kl / 2 + 1][r] = *reinterpret_cast<unsigned*>(&hp1);
            AsL2[kl / 2][r]     = bfpack(lo[0], lo[1]);
            AsL2[kl / 2 + 1][r] = bfpack(lo[2], lo[3]);
        }
        CP_ASYNC_WAIT_ALL();
        __syncthreads();
        unsigned aH[2][4], aL[2][4], bH[4][2], bL[4][2];
#pragma unroll
        for (int mt = 0; mt < 2; mt++) {
            int rb = warpM * 32 + mt * 16;
            aH[mt][0] = AsH2[qs][rb + qr];
            aH[mt][1] = AsH2[qs][rb + qr + 8];
            aH[mt][2] = AsH2[qs + 4][rb + qr];
            aH[mt][3] = AsH2[qs + 4][rb + qr + 8];
            aL[mt][0] = AsL2[qs][rb + qr];
            aL[mt][1] = AsL2[qs][rb + qr + 8];
            aL[mt][2] = AsL2[qs + 4][rb + qr];
            aL[mt][3] = AsL2[qs + 4][rb + qr + 8];
        }
#pragma unroll
        for (int nt = 0; nt < 4; nt++) {
            int cb = warpN * 32 + nt * 8;
            bH[nt][0] = WsH2[qs][cb + qr];
            bH[nt][1] = WsH2[qs + 4][cb + qr];
            bL[nt][0] = WsL2[qs][cb + qr];
            bL[nt][1] = WsL2[qs + 4][cb + qr];
        }
#pragma unroll
        for (int mt = 0; mt < 2; mt++)
#pragma unroll
            for (int nt = 0; nt < 4; nt++) {
                MMA_BF16(acc[mt][nt], aL[mt], bH[nt]);
                MMA_BF16(acc[mt][nt], aH[mt], bL[nt]);
                MMA_BF16(acc[mt][nt], aH[mt], bH[nt]);
            }
        __syncthreads();
    }
    float* cfap = (float*)g_cfa4;
#pragma unroll
    for (int nt = 0; nt < 4; nt++) {
        int colb = warpN * 32 + nt * 8 + qs * 2;
        float sc0 = g_scale_cp[colb], sc1 = g_scale_cp[colb + 1];
        float bi0 = g_bias_cp[colb], bi1 = g_bias_cp[colb + 1];
#pragma unroll
        for (int mt = 0; mt < 2; mt++)
#pragma unroll
            for (int h = 0; h < 2; h++) {
                int rr = warpM * 32 + mt * 16 + qr + h * 8;
                int c = row0 + rr;
                if (c >= Kv) continue;
                float v0 = acc[mt][nt][2 * h] * sc0 + bi0;
                v0 = (v0 >= 0.f) ? v0 : 0.1f * v0;
                float v1 = acc[mt][nt][2 * h + 1] * sc1 + bi1;
                v1 = (v1 >= 0.f) ? v1 : 0.1f * v1;
                cfap[(size_t)c * DF + colb] = v0;
                cfap[(size_t)c * DF + colb + 1] = v1;
            }
    }
}

// ---------------- per-cluster row sums of cfa (one warp per cluster) — R14-proven ----------------
__global__ void k_rowsum() {
    int Kv = g_K + 1;
    int w = (blockIdx.x * 256 + threadIdx.x) >> 5;
    if (w >= Kv) return;
    int lane = threadIdx.x & 31;
    const float* row = (const float*)g_cfa4 + (size_t)w * DF;
    float4 v = *(const float4*)&row[lane * 4];
    float s = __fadd_rn(__fadd_rn(__fadd_rn(v.x, v.y), v.z), v.w);
#pragma unroll
    for (int o = 16; o > 0; o >>= 1) s = __fadd_rn(s, __shfl_xor_sync(0xffffffffu, s, o));
    if (lane == 0) g_rowsum[w] = s;
}

// ---------------- amask + compaction: singleton clusters give exact D1==D2 ----------------
__global__ void k_amask() {
    int Kv = g_K + 1;
    int i = blockIdx.x * 256 + threadIdx.x;
    if (i >= NPTS) return;
    int c = g_inv[i];
    int a = g_arank[i];
    int c1 = g_aCl0[a], c2 = g_aCl1[a];
    bool v1 = (c1 < Kv);
    bool v2 = (c2 != c1) && (c2 < Kv);
    float S1 = v1 ? g_rowsum[c1] : 0.f;
    float S2 = v2 ? g_rowsum[c2] : 0.f;
    int cnt = (v1 ? 1 : 0) + (v2 ? 1 : 0);
    float rca = 1.0f / fmaxf((float)cnt, 1.0f);
    float D2 = __fmul_rn(__fadd_rn(S1, S2), rca);
    float D1 = (c < Kv) ? g_rowsum[c] : 0.f;
    if (__fadd_rn(D1, -D2) > 0.0f) {
        int pos = atomicAdd(&g_nMasked, 1);
        g_mlist[pos] = i;
    }
}

// ---------------- point GEMM over MASKED rows only (split-bf16, 64-row tiles) ----------------
__global__ __launch_bounds__(256) void k_pgemm(const float* __restrict__ feat,
                                               float* __restrict__ out) {
    int nM = g_nMasked;
    if (nM <= 1) return;                    // reference early-return: out already = feat
    int Kv = g_K + 1;
    int row0 = blockIdx.x * 64;
    if (row0 >= nM) return;
    __shared__ __align__(16) unsigned AsH2[8][72], AsL2[8][72];
    __shared__ __align__(16) unsigned WsH2[8][136], WsL2[8][136];
    __shared__ int gi[64];    // global point index per tile row
    __shared__ int ci[64];
    __shared__ int aC1[64];
    __shared__ int aC2[64];
    __shared__ float rca[64];
    int t = threadIdx.x;
    if (t < 64) {
        int li = min(row0 + t, nM - 1);
        int i = g_mlist[li];
        gi[t] = i;
        int c = g_inv[i];
        int a = g_arank[i];
        ci[t] = c;
        int c1 = g_aCl0[a], c2 = g_aCl1[a];
        bool v1 = (c1 < Kv);
        bool v2 = (c2 != c1) && (c2 < Kv);
        aC1[t] = v1 ? c1 : -1;
        aC2[t] = v2 ? c2 : -1;
        int cnt = (v1 ? 1 : 0) + (v2 ? 1 : 0);
        rca[t] = 1.0f / fmaxf((float)cnt, 1.0f);
    }
    __syncthreads();
    int r = t & 63, kl = (t >> 6) * 4;
    int lane = t & 31;
    int warpM = t >> 7;
    int warpN = (t >> 5) & 3;
    int qr = lane >> 2, qs = lane & 3;
    int wk2 = t >> 5, wc4 = (t & 31) * 4;
    unsigned sWH = (unsigned)__cvta_generic_to_shared(&WsH2[wk2][wc4]);
    unsigned sWL = (unsigned)__cvta_generic_to_shared(&WsL2[wk2][wc4]);
    float acc[2][4][4];
#pragma unroll
    for (int a = 0; a < 2; a++)
#pragma unroll
        for (int b = 0; b < 4; b++)
#pragma unroll
            for (int c = 0; c < 4; c++) acc[a][b][c] = 0.f;
    const float* cfap = (const float*)g_cfa4;
    int myC = ci[r], myA1 = aC1[r], myA2 = aC2[r];
    float myR = rca[r];
    int i_r = gi[r];
    for (int kt = 0; kt < 384; kt += 16) {
        CP_ASYNC16(sWH, &g_wpfH2[(size_t)(kt / 2 + wk2) * DF + wc4]);
        CP_ASYNC16(sWL, &g_wpfL2[(size_t)(kt / 2 + wk2) * DF + wc4]);
        int kk = kt + kl;
        float4 v;
        if (kk < 128) {
            v = *(const float4*)&feat[(size_t)i_r * DF + kk];
        } else if (kk < 256) {
            if (myC < Kv) v = *(const float4*)&cfap[(size_t)myC * DF + (kk - 128)];
            else v = make_float4(0.f, 0.f, 0.f, 0.f);
        } else {
            float4 s;
            if (myA1 >= 0) {
                s = *(const float4*)&cfap[(size_t)myA1 * DF + (kk - 256)];
                if (myA2 >= 0) {
                    float4 s2 = *(const float4*)&cfap[(size_t)myA2 * DF + (kk - 256)];
                    s.x = __fadd_rn(s.x, s2.x);
                    s.y = __fadd_rn(s.y, s2.y);
                    s.z = __fadd_rn(s.z, s2.z);
                    s.w = __fadd_rn(s.w, s2.w);
                }
            } else {
                s = make_float4(0.f, 0.f, 0.f, 0.f);
            }
            v.x = __fmul_rn(s.x, myR);
            v.y = __fmul_rn(s.y, myR);
            v.z = __fmul_rn(s.z, myR);
            v.w = __fmul_rn(s.w, myR);
        }
        float vv[4] = {v.x, v.y, v.z, v.w};
        float lo[4];
        __nv_bfloat16 hi[4];
#pragma unroll
        for (int j = 0; j < 4; j++) {
            hi[j] = __float2bfloat16(vv[j]);
            lo[j] = vv[j] - __bfloat162float(hi[j]);
        }
        {
            __nv_bfloat162 hp0 = __halves2bfloat162(hi[0], hi[1]);
            __nv_bfloat162 hp1 = __halves2bfloat162(hi[2], hi[3]);
            AsH2[kl / 2][r]     = *reinterpret_cast<unsigned*>(&hp0);
            AsH2[kl / 2 + 1][r] = *reinterpret_cast<unsigned*>(&hp1);
            AsL2[kl / 2][r]     = bfpack(lo[0], lo[1]);
            AsL2[kl / 2 + 1][r] = bfpack(lo[2], lo[3]);
        }
        CP_ASYNC_WAIT_ALL();
        __syncthreads();
        unsigned aH[2][4], aL[2][4], bH[4][2], bL[4][2];
#pragma unroll
        for (int mt = 0; mt < 2; mt++) {
            int rb = warpM * 32 + mt * 16;
            aH[mt][0] = AsH2[qs][rb + qr];
            aH[mt][1] = AsH2[qs][rb + qr + 8];
            aH[mt][2] = AsH2[qs + 4][rb + qr];
            aH[mt][3] = AsH2[qs + 4][rb + qr + 8];
            aL[mt][0] = AsL2[qs][rb + qr];
            aL[mt][1] = AsL2[qs][rb + qr + 8];
            aL[mt][2] = AsL2[qs + 4][rb + qr];
            aL[mt][3] = AsL2[qs + 4][rb + qr + 8];
        }
#pragma unroll
        for (int nt = 0; nt < 4; nt++) {
            int cb = warpN * 32 + nt * 8;
            bH[nt][0] = WsH2[qs][cb + qr];
            bH[nt][1] = WsH2[qs + 4][cb + qr];
            bL[nt][0] = WsL2[qs][cb + qr];
            bL[nt][1] = WsL2[qs + 4][cb + qr];
        }
#pragma unroll
        for (int mt = 0; mt < 2; mt++)
#pragma unroll
            for (int nt = 0; nt < 4; nt++) {
                MMA_BF16(acc[mt][nt], aL[mt], bH[nt]);
                MMA_BF16(acc[mt][nt], aH[mt], bL[nt]);
                MMA_BF16(acc[mt][nt], aH[mt], bH[nt]);
            }
        __syncthreads();
    }
#pragma unroll
    for (int nt = 0; nt < 4; nt++) {
        int colb = warpN * 32 + nt * 8 + qs * 2;
        float sc0 = g_scale_pf[colb], sc1 = g_scale_pf[colb + 1];
        float bi0 = g_bias_pf[colb], bi1 = g_bias_pf[colb + 1];
#pragma unroll
        for (int mt = 0; mt < 2; mt++)
#pragma unroll
            for (int h = 0; h < 2; h++) {
                int rr = warpM * 32 + mt * 16 + qr + h * 8;
                if (row0 + rr >= nM) continue;
                int i = gi[rr];
                float v0 = acc[mt][nt][2 * h] * sc0 + bi0;
                v0 = (v0 >= 0.f) ? v0 : 0.1f * v0;
                float v1 = acc[mt][nt][2 * h + 1] * sc1 + bi1;
                v1 = (v1 >= 0.f) ? v1 : 0.1f * v1;
                __stcs((float2*)&out[(size_t)i * DF + colb], make_float2(v0, v1));
            }
    }
}

// ---------------- launch ----------------
extern "C" void kernel_launch(void* const* d_in, const int* in_sizes, int n_in,
                              void* d_out, int out_size) {
    const float* feat  = (const float*)d_in[0];
    const float* pc    = (const float*)d_in[1];
    const int*   bidx  = (const int*)d_in[2];
    const void*  maskp = d_in[3];
    // d_in[4] timestamp: net contribution is exactly zero in the reference
    const float* w_pf  = (const float*)d_in[5];
    const float* b_pf  = (const float*)d_in[6];
    const float* gm_pf = (const float*)d_in[7];
    const float* be_pf = (const float*)d_in[8];
    const float* m_pf  = (const float*)d_in[9];
    const float* v_pf  = (const float*)d_in[10];
    const float* w_cp  = (const float*)d_in[11];
    const float* b_cp  = (const float*)d_in[12];
    const float* gm_cp = (const float*)d_in[13];
    const float* be_cp = (const float*)d_in[14];
    const float* m_cp  = (const float*)d_in[15];
    const float* v_cp  = (const float*)d_in[16];
    float* out = (float*)d_out;

    k_zerobits<<<458, 256>>>();
    int phaseA_grid = MARK_BLOCKS + WSPLIT_BLOCKS + 2 + ZERO_BLOCKS;
    k_phaseA<<<phaseA_grid, 256>>>(pc, bidx, (const int*)maskp, w_pf, w_cp,
                                   b_pf, gm_pf, be_pf, m_pf, v_pf,
                                   b_cp, gm_cp, be_cp, m_cp, v_cp);
    k_scan1<<<VBLOCKS + ABLOCKS, 256>>>();
    k_scan2<<<2, 1024>>>();
    k_featacc<<<(NPTS * 32 + 255) / 256, 256>>>(feat, maskp, out);
    k_cgemm<<<GEMM_BLOCKS, 256>>>();
    k_rowsum<<<(NPTS * 32 + 255) / 256, 256>>>();
    k_amask<<<MARK_BLOCKS, 256>>>();
    k_pgemm<<<GEMM_BLOCKS, 256>>>(feat, out);
}

// round 17
// speedup vs baseline: 1.7915x; 1.7915x over previous
#include <cuda_runtime.h>
#include <cuda_bf16.h>
#include <math.h>

// ---------------- problem constants ----------------
#define NPTS   200000
#define DF     128
#define NXC    250
#define NYC    250
#define NZC    20
#define VXYZ   1250000           // NXC*NYC*NZC
#define NVKEY  10000000          // B * VXYZ
#define NAKEY  5000000           // (B/2) * VXYZ
#define VWORDS 312500            // NVKEY/32
#define AWORDS 156250            // NAKEY/32
#define VBLOCKS 1221             // ceil(VWORDS/256)
#define ABLOCKS 611              // ceil(AWORDS/256)
#define MARK_BLOCKS 782          // ceil(NPTS/256)
#define WSPLIT_BLOCKS 96         // (3*DF/2*DF)/256
#define ZERO_BLOCKS 1024
#define GEMM_BLOCKS 3125         // NPTS/64  (64-row tiles)

// ---------------- device scratch (no allocs allowed) ----------------
__device__ unsigned g_bitV[VWORDS];
__device__ unsigned g_bitA[AWORDS];
__device__ int g_prefV[VWORDS];
__device__ int g_prefA[AWORDS];
__device__ int g_blkV[VBLOCKS];
__device__ int g_blkA[ABLOCKS];
__device__ int g_vkey[NPTS];
__device__ int g_akey[NPTS];
__device__ int g_inv[NPTS];
__device__ int g_arank[NPTS];
__device__ int g_aCl0[NPTS];   // min cluster id per associate voxel
__device__ int g_aCl1[NPTS];   // max cluster id per associate voxel (<= 2 clusters/assoc)
__device__ float g_cnt[NPTS];
__device__ float g_rowsum[NPTS];            // per-cluster sum of cfa row
__device__ int g_mlist[NPTS];               // compacted masked point indices
__device__ int g_nMasked;
__device__ float4 g_csum4[NPTS * DF / 4];   // cluster feature sums
__device__ float4 g_cfa4[NPTS * DF / 4];    // projected cluster features
__device__ int g_K;            // max foreground inv (K = g_K+1)
__device__ int g_maskFmt;      // 0=int32, 1=byte, 2=float32
__device__ float g_scale_cp[DF], g_bias_cp[DF], g_scale_pf[DF], g_bias_pf[DF];
// pre-split weights, bf16 hi/lo planes packed as bf162 pairs along K
__device__ unsigned g_wpfH2[(3 * DF / 2) * DF], g_wpfL2[(3 * DF / 2) * DF];
__device__ unsigned g_wcpH2[(DF / 2) * DF],     g_wcpL2[(DF / 2) * DF];

// ---------------- helpers ----------------
__device__ __forceinline__ unsigned bfpack(float a, float b) {
    __nv_bfloat162 p = __halves2bfloat162(__float2bfloat16(a), __float2bfloat16(b));
    return *reinterpret_cast<unsigned*>(&p);
}

#define MMA_BF16(d, a, b) \
    asm volatile("mma.sync.aligned.m16n8k16.row.col.f32.bf16.bf16.f32 " \
                 "{%0,%1,%2,%3}, {%4,%5,%6,%7}, {%8,%9}, {%0,%1,%2,%3};\n" \
                 : "+f"((d)[0]), "+f"((d)[1]), "+f"((d)[2]), "+f"((d)[3]) \
                 : "r"((a)[0]), "r"((a)[1]), "r"((a)[2]), "r"((a)[3]), \
                   "r"((b)[0]), "r"((b)[1]))

#define CP_ASYNC16(smem_u32, gptr) \
    asm volatile("cp.async.ca.shared.global [%0], [%1], 16;" \
                 :: "r"(smem_u32), "l"(gptr) : "memory")
#define CP_ASYNC_WAIT_ALL() \
    asm volatile("cp.async.commit_group;\ncp.async.wait_group 0;" ::: "memory")

__device__ __forceinline__ bool get_fg(const void* m, int i) {
    int f = g_maskFmt;
    if (f == 0) return ((const int*)m)[i] != 0;
    if (f == 2) return ((const float*)m)[i] != 0.0f;
    return ((const unsigned char*)m)[i] != 0;
}

// ---------------- bitmap zeroing (MUST precede k_phaseA's atomicOr marks) ----------------
__global__ void k_zerobits() {
    int t = blockIdx.x * 256 + threadIdx.x;
    int stride = gridDim.x * 256;
    for (int k = t; k < VWORDS; k += stride) g_bitV[k] = 0u;
    for (int k = t; k < AWORDS; k += stride) g_bitA[k] = 0u;
}

// ---------------- phase A: mark | wsplit | detect | prep | acc-zero (fused) ----------------
__global__ void k_phaseA(const float* __restrict__ pc, const int* __restrict__ bidx,
                         const int* __restrict__ maskI,
                         const float* __restrict__ w_pf, const float* __restrict__ w_cp,
                         const float* __restrict__ b_pf, const float* __restrict__ gm_pf,
                         const float* __restrict__ be_pf, const float* __restrict__ m_pf,
                         const float* __restrict__ v_pf,
                         const float* __restrict__ b_cp, const float* __restrict__ gm_cp,
                         const float* __restrict__ be_cp, const float* __restrict__ m_cp,
                         const float* __restrict__ v_cp) {
    int b = blockIdx.x;
    int t = threadIdx.x;
    if (b < MARK_BLOCKS) {
        // ---- voxelize + mark bitmaps ----
        int i = b * 256 + t;
        if (i >= NPTS) return;
        float x = pc[3 * i + 0], y = pc[3 * i + 1], z = pc[3 * i + 2];
        int xi = (int)floorf(__fdiv_rn(x - (-50.0f), 0.4f));
        int yi = (int)floorf(__fdiv_rn(y - (-50.0f), 0.4f));
        int zi = (int)floorf(__fdiv_rn(z - (-5.0f), 0.4f));
        xi = min(max(xi, 0), NXC - 1);
        yi = min(max(yi, 0), NYC - 1);
        zi = min(max(zi, 0), NZC - 1);
        int bb = bidx[i];
        int local = (xi * NYC + yi) * NZC + zi;
        int vk = bb * VXYZ + local;
        int ak = (bb >> 1) * VXYZ + local;
        g_vkey[i] = vk;
        g_akey[i] = ak;
        atomicOr(&g_bitV[vk >> 5], 1u << (vk & 31));
        atomicOr(&g_bitA[ak >> 5], 1u << (ak & 31));
    } else if (b < MARK_BLOCKS + WSPLIT_BLOCKS) {
        // ---- weight split into bf16 hi/lo packed planes ----
        int idx = (b - MARK_BLOCKS) * 256 + t;
        if (idx < (3 * DF / 2) * DF) {
            int k2 = idx / DF, col = idx % DF;
            float x0 = w_pf[(2 * k2) * DF + col];
            float x1 = w_pf[(2 * k2 + 1) * DF + col];
            __nv_bfloat16 h0 = __float2bfloat16(x0);
            __nv_bfloat16 h1 = __float2bfloat16(x1);
            __nv_bfloat162 hp = __halves2bfloat162(h0, h1);
            g_wpfH2[idx] = *reinterpret_cast<unsigned*>(&hp);
            g_wpfL2[idx] = bfpack(x0 - __bfloat162float(h0), x1 - __bfloat162float(h1));
        }
        if (idx < (DF / 2) * DF) {
            int k2 = idx / DF, col = idx % DF;
            float x0 = w_cp[(2 * k2) * DF + col];
            float x1 = w_cp[(2 * k2 + 1) * DF + col];
            __nv_bfloat16 h0 = __float2bfloat16(x0);
            __nv_bfloat16 h1 = __float2bfloat16(x1);
            __nv_bfloat162 hp = __halves2bfloat162(h0, h1);
            g_wcpH2[idx] = *reinterpret_cast<unsigned*>(&hp);
            g_wcpL2[idx] = bfpack(x0 - __bfloat162float(h0), x1 - __bfloat162float(h1));
        }
    } else if (b == MARK_BLOCKS + WSPLIT_BLOCKS) {
        // ---- mask dtype detection ----
        int notInt = 0, notFloat = 0;
        for (int k = t; k < 1000; k += 256) {
            unsigned u = (unsigned)maskI[k];
            if (u > 1u) notInt = 1;
            if (u != 0u && u != 0x3F800000u) notFloat = 1;
        }
        notInt = __syncthreads_or(notInt);
        notFloat = __syncthreads_or(notFloat);
        if (t == 0) {
            int fmt;
            if (!notInt) fmt = 0;
            else if (!notFloat) fmt = 2;
            else fmt = 1;
            g_maskFmt = fmt;
        }
    } else if (b == MARK_BLOCKS + WSPLIT_BLOCKS + 1) {
        // ---- fold BN constants ----
        if (t < DF) {
            float s = gm_cp[t] * rsqrtf(v_cp[t] + 1e-5f);
            g_scale_cp[t] = s;
            g_bias_cp[t] = (b_cp[t] - m_cp[t]) * s + be_cp[t];
            float s2 = gm_pf[t] * rsqrtf(v_pf[t] + 1e-5f);
            g_scale_pf[t] = s2;
            g_bias_pf[t] = (b_pf[t] - m_pf[t]) * s2 + be_pf[t];
        }
        if (t == 0) { g_K = -1; g_nMasked = 0; }
    } else {
        // ---- zero-init of accumulators (consumed only by LATER launches; no race) ----
        int zb = b - (MARK_BLOCKS + WSPLIT_BLOCKS + 2);
        int idx = zb * 256 + t;
        int stride = ZERO_BLOCKS * 256;
        float4 z = make_float4(0.f, 0.f, 0.f, 0.f);
        for (int k = idx; k < NPTS * DF / 4; k += stride) g_csum4[k] = z;
        for (int k = idx; k < NPTS; k += stride) {
            g_cnt[k] = 0.f;
            g_aCl0[k] = 0x7FFFFFFF;
            g_aCl1[k] = -1;
        }
    }
}

// ---------------- bitmap popcount scan phase 1 (V and A fused) ----------------
__global__ void k_scan1() {
    int which = (blockIdx.x >= VBLOCKS) ? 1 : 0;
    int bb = which ? (blockIdx.x - VBLOCKS) : blockIdx.x;
    const unsigned* bits = which ? g_bitA : g_bitV;
    int* pref = which ? g_prefA : g_prefV;
    int* blks = which ? g_blkA : g_blkV;
    int nwords = which ? AWORDS : VWORDS;
    int w = bb * 256 + threadIdx.x;
    int c = (w < nwords) ? __popc(bits[w]) : 0;
    int lane = threadIdx.x & 31, wid = threadIdx.x >> 5;
    int v = c;
#pragma unroll
    for (int o = 1; o < 32; o <<= 1) { int u = __shfl_up_sync(0xffffffffu, v, o); if (lane >= o) v += u; }
    __shared__ int ws[8];
    if (lane == 31) ws[wid] = v;
    __syncthreads();
    if (wid == 0) {
        int x = (lane < 8) ? ws[lane] : 0;
#pragma unroll
        for (int o = 1; o < 8; o <<= 1) { int u = __shfl_up_sync(0xffffffffu, x, o); if (lane >= o) x += u; }
        if (lane < 8) ws[lane] = x;
    }
    __syncthreads();
    int incl = v + (wid > 0 ? ws[wid - 1] : 0);
    if (w < nwords) pref[w] = incl - c;
    if (threadIdx.x == 255) blks[bb] = incl;
}

// ---------------- scan phase 2 (V and A fused; 2 blocks) ----------------
__global__ void k_scan2() {
    int which = blockIdx.x;
    int nb = which ? ABLOCKS : VBLOCKS;
    int* blk = which ? g_blkA : g_blkV;
    int t = threadIdx.x;
    int i0 = 2 * t, i1 = 2 * t + 1;
    int v0 = (i0 < nb) ? blk[i0] : 0;
    int v1 = (i1 < nb) ? blk[i1] : 0;
    int s = v0 + v1;
    int lane = t & 31, wid = t >> 5;
    int v = s;
#pragma unroll
    for (int o = 1; o < 32; o <<= 1) { int u = __shfl_up_sync(0xffffffffu, v, o); if (lane >= o) v += u; }
    __shared__ int ws[32];
    if (lane == 31) ws[wid] = v;
    __syncthreads();
    if (wid == 0) {
        int x = ws[lane];
#pragma unroll
        for (int o = 1; o < 32; o <<= 1) { int u = __shfl_up_sync(0xffffffffu, x, o); if (lane >= o) x += u; }
        ws[lane] = x;
    }
    __syncthreads();
    int incl = v + (wid > 0 ? ws[wid - 1] : 0);
    int ex = incl - s;
    if (i0 < nb) blk[i0] = ex;
    if (i1 < nb) blk[i1] = ex + v0;
}

// ---------------- per-point ranks (scan phase-3 folded in) + assoc-pair build ----------------
__global__ void k_rank(const void* __restrict__ maskp) {
    int i = blockIdx.x * 256 + threadIdx.x;
    if (i >= NPTS) return;
    int vk = g_vkey[i], ak = g_akey[i];
    int wv = vk >> 5, wa = ak >> 5;
    int c = g_prefV[wv] + g_blkV[wv >> 8] + __popc(g_bitV[wv] & ((1u << (vk & 31)) - 1u));
    int a = g_prefA[wa] + g_blkA[wa >> 8] + __popc(g_bitA[wa] & ((1u << (ak & 31)) - 1u));
    g_inv[i] = c;
    g_arank[i] = a;
    atomicMin(&g_aCl0[a], c);
    atomicMax(&g_aCl1[a], c);
    if (get_fg(maskp, i)) atomicMax(&g_K, c);
}

// ---------------- foreground scatter-sum + default out=feat copy (fused) ----------------
__global__ void k_featacc(const float* __restrict__ feat, const void* __restrict__ maskp,
                          float* __restrict__ out) {
    int t = blockIdx.x * 256 + threadIdx.x;
    int i = t >> 5;
    if (i >= NPTS) return;
    int j = (t & 31) * 4;
    float4 f = __ldcs((const float4*)&feat[(size_t)i * DF + j]);
    __stcs((float4*)&out[(size_t)i * DF + j], f);   // default: out = feat (pgemm overwrites masked rows)
    if (!get_fg(maskp, i)) return;
    int c = g_inv[i];
    float* cs = (float*)g_csum4 + (size_t)c * DF + j;
    atomicAdd(cs + 0, f.x);
    atomicAdd(cs + 1, f.y);
    atomicAdd(cs + 2, f.z);
    atomicAdd(cs + 3, f.w);
    if ((t & 31) == 0) atomicAdd(&g_cnt[c], 1.0f);
}

// ---------------- cluster GEMM (split-bf16, 64-row tiles) — R14-proven ----------------
__global__ __launch_bounds__(256) void k_cgemm() {
    int Kv = g_K + 1;
    int row0 = blockIdx.x * 64;
    if (row0 >= Kv) return;
    __shared__ __align__(16) unsigned AsH2[8][72], AsL2[8][72];     // [k2][row] bf162
    __shared__ __align__(16) unsigned WsH2[8][136], WsL2[8][136];   // [k2][col] bf162
    __shared__ float rcs[64];
    int t = threadIdx.x;
    if (t < 64) {
        int c = row0 + t;
        rcs[t] = 1.0f / fmaxf(g_cnt[c], 1.0f);
    }
    __syncthreads();
    int r = t & 63, kl = (t >> 6) * 4;
    int lane = t & 31;
    int warpM = t >> 7;          // 0..1
    int warpN = (t >> 5) & 3;    // 0..3
    int qr = lane >> 2, qs = lane & 3;
    int wk2 = t >> 5, wc4 = (t & 31) * 4;
    unsigned sWH = (unsigned)__cvta_generic_to_shared(&WsH2[wk2][wc4]);
    unsigned sWL = (unsigned)__cvta_generic_to_shared(&WsL2[wk2][wc4]);
    float acc[2][4][4];
#pragma unroll
    for (int a = 0; a < 2; a++)
#pragma unroll
        for (int b = 0; b < 4; b++)
#pragma unroll
            for (int c = 0; c < 4; c++) acc[a][b][c] = 0.f;
    const float* csp = (const float*)g_csum4;
    for (int kt = 0; kt < 128; kt += 16) {
        CP_ASYNC16(sWH, &g_wcpH2[(kt / 2 + wk2) * DF + wc4]);
        CP_ASYNC16(sWL, &g_wcpL2[(kt / 2 + wk2) * DF + wc4]);
        float4 av = __ldcs((const float4*)&csp[(size_t)(row0 + r) * DF + kt + kl]);
        float rc = rcs[r];
        float vv[4] = {av.x * rc, av.y * rc, av.z * rc, av.w * rc};
        float lo[4];
        __nv_bfloat16 hi[4];
#pragma unroll
        for (int j = 0; j < 4; j++) {
            hi[j] = __float2bfloat16(vv[j]);
            lo[j] = vv[j] - __bfloat162float(hi[j]);
        }
        {
            __nv_bfloat162 hp0 = __halves2bfloat162(hi[0], hi[1]);
            __nv_bfloat162 hp1 = __halves2bfloat162(hi[2], hi[3]);
            AsH2[kl / 2][r]     = *reinterpret_cast<unsigned*>(&hp0);
            AsH2[kl / 2 + 1][r] = *reinterpret_cast<unsigned*>(&hp1);
            AsL2[kl / 2][r]     = bfpack(lo[0], lo[1]);
            AsL2[kl / 2 + 1][r] = bfpack(lo[2], lo[3]);
        }
        CP_ASYNC_WAIT_ALL();
        __syncthreads();
        unsigned aH[2][4], aL[2][4], bH[4][2], bL[4][2];
#pragma unroll
        for (int mt = 0; mt < 2; mt++) {
            int rb = warpM * 32 + mt * 16;
            aH[mt][0] = AsH2[qs][rb + qr];
            aH[mt][1] = AsH2[qs][rb + qr + 8];
            aH[mt][2] = AsH2[qs + 4][rb + qr];
            aH[mt][3] = AsH2[qs + 4][rb + qr + 8];
            aL[mt][0] = AsL2[qs][rb + qr];
            aL[mt][1] = AsL2[qs][rb + qr + 8];
            aL[mt][2] = AsL2[qs + 4][rb + qr];
            aL[mt][3] = AsL2[qs + 4][rb + qr + 8];
        }
#pragma unroll
        for (int nt = 0; nt < 4; nt++) {
            int cb = warpN * 32 + nt * 8;
            bH[nt][0] = WsH2[qs][cb + qr];
            bH[nt][1] = WsH2[qs + 4][cb + qr];
            bL[nt][0] = WsL2[qs][cb + qr];
            bL[nt][1] = WsL2[qs + 4][cb + qr];
        }
#pragma unroll
        for (int mt = 0; mt < 2; mt++)
#pragma unroll
            for (int nt = 0; nt < 4; nt++) {
                MMA_BF16(acc[mt][nt], aL[mt], bH[nt]);
                MMA_BF16(acc[mt][nt], aH[mt], bL[nt]);
                MMA_BF16(acc[mt][nt], aH[mt], bH[nt]);
            }
        __syncthreads();
    }
    float* cfap = (float*)g_cfa4;
#pragma unroll
    for (int nt = 0; nt < 4; nt++) {
        int colb = warpN * 32 + nt * 8 + qs * 2;
        float sc0 = g_scale_cp[colb], sc1 = g_scale_cp[colb + 1];
        float bi0 = g_bias_cp[colb], bi1 = g_bias_cp[colb + 1];
#pragma unroll
        for (int mt = 0; mt < 2; mt++)
#pragma unroll
            for (int h = 0; h < 2; h++) {
                int rr = warpM * 32 + mt * 16 + qr + h * 8;
                int c = row0 + rr;
                if (c >= Kv) continue;
                float v0 = acc[mt][nt][2 * h] * sc0 + bi0;
                v0 = (v0 >= 0.f) ? v0 : 0.1f * v0;
                float v1 = acc[mt][nt][2 * h + 1] * sc1 + bi1;
                v1 = (v1 >= 0.f) ? v1 : 0.1f * v1;
                cfap[(size_t)c * DF + colb] = v0;
                cfap[(size_t)c * DF + colb + 1] = v1;
            }
    }
}

// ---------------- per-cluster row sums of cfa (one warp per cluster) — R14-proven ----------------
__global__ void k_rowsum() {
    int Kv = g_K + 1;
    int w = (blockIdx.x * 256 + threadIdx.x) >> 5;
    if (w >= Kv) return;
    int lane = threadIdx.x & 31;
    const float* row = (const float*)g_cfa4 + (size_t)w * DF;
    float4 v = *(const float4*)&row[lane * 4];
    float s = __fadd_rn(__fadd_rn(__fadd_rn(v.x, v.y), v.z), v.w);
#pragma unroll
    for (int o = 16; o > 0; o >>= 1) s = __fadd_rn(s, __shfl_xor_sync(0xffffffffu, s, o));
    if (lane == 0) g_rowsum[w] = s;
}

// ---------------- amask + compaction: singleton clusters give exact D1==D2 ----------------
__global__ void k_amask() {
    int Kv = g_K + 1;
    int i = blockIdx.x * 256 + threadIdx.x;
    if (i >= NPTS) return;
    int c = g_inv[i];
    int a = g_arank[i];
    int c1 = g_aCl0[a], c2 = g_aCl1[a];
    bool v1 = (c1 < Kv);
    bool v2 = (c2 != c1) && (c2 < Kv);
    float S1 = v1 ? g_rowsum[c1] : 0.f;
    float S2 = v2 ? g_rowsum[c2] : 0.f;
    int cnt = (v1 ? 1 : 0) + (v2 ? 1 : 0);
    float rca = 1.0f / fmaxf((float)cnt, 1.0f);
    float D2 = __fmul_rn(__fadd_rn(S1, S2), rca);
    float D1 = (c < Kv) ? g_rowsum[c] : 0.f;
    if (__fadd_rn(D1, -D2) > 0.0f) {
        int pos = atomicAdd(&g_nMasked, 1);
        g_mlist[pos] = i;
    }
}

// ---------------- point GEMM over MASKED rows only (split-bf16, 64-row tiles) ----------------
__global__ __launch_bounds__(256) void k_pgemm(const float* __restrict__ feat,
                                               float* __restrict__ out) {
    int nM = g_nMasked;
    if (nM <= 1) return;                    // reference early-return: out already = feat
    int Kv = g_K + 1;
    int row0 = blockIdx.x * 64;
    if (row0 >= nM) return;
    __shared__ __align__(16) unsigned AsH2[8][72], AsL2[8][72];
    __shared__ __align__(16) unsigned WsH2[8][136], WsL2[8][136];
    __shared__ int gi[64];    // global point index per tile row
    __shared__ int ci[64];
    __shared__ int aC1[64];
    __shared__ int aC2[64];
    __shared__ float rca[64];
    int t = threadIdx.x;
    if (t < 64) {
        int li = min(row0 + t, nM - 1);
        int i = g_mlist[li];
        gi[t] = i;
        int c = g_inv[i];
        int a = g_arank[i];
        ci[t] = c;
        int c1 = g_aCl0[a], c2 = g_aCl1[a];
        bool v1 = (c1 < Kv);
        bool v2 = (c2 != c1) && (c2 < Kv);
        aC1[t] = v1 ? c1 : -1;
        aC2[t] = v2 ? c2 : -1;
        int cnt = (v1 ? 1 : 0) + (v2 ? 1 : 0);
        rca[t] = 1.0f / fmaxf((float)cnt, 1.0f);
    }
    __syncthreads();
    int r = t & 63, kl = (t >> 6) * 4;
    int lane = t & 31;
    int warpM = t >> 7;
    int warpN = (t >> 5) & 3;
    int qr = lane >> 2, qs = lane & 3;
    int wk2 = t >> 5, wc4 = (t & 31) * 4;
    unsigned sWH = (unsigned)__cvta_generic_to_shared(&WsH2[wk2][wc4]);
    unsigned sWL = (unsigned)__cvta_generic_to_shared(&WsL2[wk2][wc4]);
    float acc[2][4][4];
#pragma unroll
    for (int a = 0; a < 2; a++)
#pragma unroll
        for (int b = 0; b < 4; b++)
#pragma unroll
            for (int c = 0; c < 4; c++) acc[a][b][c] = 0.f;
    const float* cfap = (const float*)g_cfa4;
    int myC = ci[r], myA1 = aC1[r], myA2 = aC2[r];
    float myR = rca[r];
    int i_r = gi[r];
    for (int kt = 0; kt < 384; kt += 16) {
        CP_ASYNC16(sWH, &g_wpfH2[(size_t)(kt / 2 + wk2) * DF + wc4]);
        CP_ASYNC16(sWL, &g_wpfL2[(size_t)(kt / 2 + wk2) * DF + wc4]);
        int kk = kt + kl;
        float4 v;
        if (kk < 128) {
            v = *(const float4*)&feat[(size_t)i_r * DF + kk];
        } else if (kk < 256) {
            if (myC < Kv) v = *(const float4*)&cfap[(size_t)myC * DF + (kk - 128)];
            else v = make_float4(0.f, 0.f, 0.f, 0.f);
        } else {
            float4 s;
            if (myA1 >= 0) {
                s = *(const float4*)&cfap[(size_t)myA1 * DF + (kk - 256)];
                if (myA2 >= 0) {
                    float4 s2 = *(const float4*)&cfap[(size_t)myA2 * DF + (kk - 256)];
                    s.x = __fadd_rn(s.x, s2.x);
                    s.y = __fadd_rn(s.y, s2.y);
                    s.z = __fadd_rn(s.z, s2.z);
                    s.w = __fadd_rn(s.w, s2.w);
                }
            } else {
                s = make_float4(0.f, 0.f, 0.f, 0.f);
            }
            v.x = __fmul_rn(s.x, myR);
            v.y = __fmul_rn(s.y, myR);
            v.z = __fmul_rn(s.z, myR);
            v.w = __fmul_rn(s.w, myR);
        }
        float vv[4] = {v.x, v.y, v.z, v.w};
        float lo[4];
        __nv_bfloat16 hi[4];
#pragma unroll
        for (int j = 0; j < 4; j++) {
            hi[j] = __float2bfloat16(vv[j]);
            lo[j] = vv[j] - __bfloat162float(hi[j]);
        }
        {
            __nv_bfloat162 hp0 = __halves2bfloat162(hi[0], hi[1]);
            __nv_bfloat162 hp1 = __halves2bfloat162(hi[2], hi[3]);
            AsH2[kl / 2][r]     = *reinterpret_cast<unsigned*>(&hp0);
            AsH2[kl / 2 + 1][r] = *reinterpret_cast<unsigned*>(&hp1);
            AsL2[kl / 2][r]     = bfpack(lo[0], lo[1]);
            AsL2[kl / 2 + 1][r] = bfpack(lo[2], lo[3]);
        }
        CP_ASYNC_WAIT_ALL();
        __syncthreads();
        unsigned aH[2][4], aL[2][4], bH[4][2], bL[4][2];
#pragma unroll
        for (int mt = 0; mt < 2; mt++) {
            int rb = warpM * 32 + mt * 16;
            aH[mt][0] = AsH2[qs][rb + qr];
            aH[mt][1] = AsH2[qs][rb + qr + 8];
            aH[mt][2] = AsH2[qs + 4][rb + qr];
            aH[mt][3] = AsH2[qs + 4][rb + qr + 8];
            aL[mt][0] = AsL2[qs][rb + qr];
            aL[mt][1] = AsL2[qs][rb + qr + 8];
            aL[mt][2] = AsL2[qs + 4][rb + qr];
            aL[mt][3] = AsL2[qs + 4][rb + qr + 8];
        }
#pragma unroll
        for (int nt = 0; nt < 4; nt++) {
            int cb = warpN * 32 + nt * 8;
            bH[nt][0] = WsH2[qs][cb + qr];
            bH[nt][1] = WsH2[qs + 4][cb + qr];
            bL[nt][0] = WsL2[qs][cb + qr];
            bL[nt][1] = WsL2[qs + 4][cb + qr];
        }
#pragma unroll
        for (int mt = 0; mt < 2; mt++)
#pragma unroll
            for (int nt = 0; nt < 4; nt++) {
                MMA_BF16(acc[mt][nt], aL[mt], bH[nt]);
                MMA_BF16(acc[mt][nt], aH[mt], bL[nt]);
                MMA_BF16(acc[mt][nt], aH[mt], bH[nt]);
            }
        __syncthreads();
    }
#pragma unroll
    for (int nt = 0; nt < 4; nt++) {
        int colb = warpN * 32 + nt * 8 + qs * 2;
        float sc0 = g_scale_pf[colb], sc1 = g_scale_pf[colb + 1];
        float bi0 = g_bias_pf[colb], bi1 = g_bias_pf[colb + 1];
#pragma unroll
        for (int mt = 0; mt < 2; mt++)
#pragma unroll
            for (int h = 0; h < 2; h++) {
                int rr = warpM * 32 + mt * 16 + qr + h * 8;
                if (row0 + rr >= nM) continue;
                int i = gi[rr];
                float v0 = acc[mt][nt][2 * h] * sc0 + bi0;
                v0 = (v0 >= 0.f) ? v0 : 0.1f * v0;
                float v1 = acc[mt][nt][2 * h + 1] * sc1 + bi1;
                v1 = (v1 >= 0.f) ? v1 : 0.1f * v1;
                __stcs((float2*)&out[(size_t)i * DF + colb], make_float2(v0, v1));
            }
    }
}

// ---------------- launch ----------------
extern "C" void kernel_launch(void* const* d_in, const int* in_sizes, int n_in,
                              void* d_out, int out_size) {
    const float* feat  = (const float*)d_in[0];
    const float* pc    = (const float*)d_in[1];
    const int*   bidx  = (const int*)d_in[2];
    const void*  maskp = d_in[3];
    // d_in[4] timestamp: net contribution is exactly zero in the reference
    const float* w_pf  = (const float*)d_in[5];
    const float* b_pf  = (const float*)d_in[6];
    const float* gm_pf = (const float*)d_in[7];
    const float* be_pf = (const float*)d_in[8];
    const float* m_pf  = (const float*)d_in[9];
    const float* v_pf  = (const float*)d_in[10];
    const float* w_cp  = (const float*)d_in[11];
    const float* b_cp  = (const float*)d_in[12];
    const float* gm_cp = (const float*)d_in[13];
    const float* be_cp = (const float*)d_in[14];
    const float* m_cp  = (const float*)d_in[15];
    const float* v_cp  = (const float*)d_in[16];
    float* out = (float*)d_out;

    k_zerobits<<<458, 256>>>();
    int phaseA_grid = MARK_BLOCKS + WSPLIT_BLOCKS + 2 + ZERO_BLOCKS;
    k_phaseA<<<phaseA_grid, 256>>>(pc, bidx, (const int*)maskp, w_pf, w_cp,
                                   b_pf, gm_pf, be_pf, m_pf, v_pf,
                                   b_cp, gm_cp, be_cp, m_cp, v_cp);
    k_scan1<<<VBLOCKS + ABLOCKS, 256>>>();
    k_scan2<<<2, 1024>>>();
    k_rank<<<MARK_BLOCKS, 256>>>(maskp);
    k_featacc<<<(NPTS * 32 + 255) / 256, 256>>>(feat, maskp, out);
    k_cgemm<<<GEMM_BLOCKS, 256>>>();
    k_rowsum<<<(NPTS * 32 + 255) / 256, 256>>>();
    k_amask<<<MARK_BLOCKS, 256>>>();
    k_pgemm<<<GEMM_BLOCKS, 256>>>(feat, out);
}